// round 6
// baseline (speedup 1.0000x reference)
#include <cuda_runtime.h>
#include <cuda_bf16.h>
#include <math.h>

// Problem constants
#define BT      2
#define ST      2048
#define T_TOK   4096          // B*S
#define H_DIM   1024
#define I_DIM   2048
#define E_NUM   8
#define TOPK    2
#define NSLOT   (T_TOK * TOPK)   // 8192 assignment rows total (always exactly this)

#define BM 64
#define BN 128
#define BK 16
#define MAX_ROW_TILES 136   // ceil(8192/64) + (E-1) worst case

// ---------------- scratch (device globals: no allocation allowed) ----------------
__device__ int   g_cnt[E_NUM];
__device__ int   g_off[E_NUM + 1];
__device__ int   g_tok_exp[NSLOT];
__device__ float g_tok_wt[NSLOT];
__device__ int   g_tok_rank[NSLOT];
__device__ int   g_perm[NSLOT];       // slot -> token
__device__ float g_pwt[NSLOT];        // slot -> routing weight
__device__ float g_hidden[(size_t)NSLOT * I_DIM];   // 64 MB intermediate

// ---------------- packed f32x2 helpers ----------------
#define PACK2(d, s) \
    asm("mov.b64 %0, {%1, %1};" : "=l"(d) : "f"(s))
#define UNPACK2(lo, hi, v) \
    asm("mov.b64 {%0, %1}, %2;" : "=f"(lo), "=f"(hi) : "l"(v))
#define FMA2(acc, a, b) \
    asm("fma.rn.f32x2 %0, %1, %2, %0;" : "+l"(acc) : "l"(a), "l"(b))

// ---------------- small kernels ----------------
__global__ void zero_cnt_kernel() {
    if (threadIdx.x < E_NUM) g_cnt[threadIdx.x] = 0;
}

__global__ void scan_off_kernel() {
    if (threadIdx.x == 0) {
        int a = 0;
        for (int e = 0; e < E_NUM; e++) { g_off[e] = a; a += g_cnt[e]; }
        g_off[E_NUM] = a;
    }
}

__global__ void build_perm_kernel() {
    int idx = blockIdx.x * blockDim.x + threadIdx.x;
    if (idx < NSLOT) {
        int e = g_tok_exp[idx];
        int slot = g_off[e] + g_tok_rank[idx];
        g_perm[slot] = idx >> 1;
        g_pwt[slot]  = g_tok_wt[idx];
    }
}

// Router: one block per token, one warp per expert (E=8 warps = 256 threads)
__global__ void router_kernel(const float* __restrict__ x,
                              const float* __restrict__ rw,
                              float* __restrict__ logits_out,
                              int write_logits) {
    int t = blockIdx.x;
    int warp = threadIdx.x >> 5, lane = threadIdx.x & 31;
    const float* xr = x + (size_t)t * H_DIM;
    float s = 0.f;
    for (int h = lane; h < H_DIM; h += 32)
        s += xr[h] * rw[h * E_NUM + warp];
#pragma unroll
    for (int o = 16; o; o >>= 1) s += __shfl_xor_sync(0xffffffffu, s, o);

    __shared__ float lg[E_NUM];
    if (lane == 0) lg[warp] = s;
    __syncthreads();

    if (threadIdx.x == 0) {
        float l[E_NUM], mx = -1e30f;
#pragma unroll
        for (int e = 0; e < E_NUM; e++) { l[e] = lg[e]; mx = fmaxf(mx, l[e]); }
        float p[E_NUM], sum = 0.f;
#pragma unroll
        for (int e = 0; e < E_NUM; e++) { p[e] = expf(l[e] - mx); sum += p[e]; }
#pragma unroll
        for (int e = 0; e < E_NUM; e++) p[e] /= sum;

        int i1 = 0;
#pragma unroll
        for (int e = 1; e < E_NUM; e++) if (p[e] > p[i1]) i1 = e;
        int i2 = (i1 == 0) ? 1 : 0;
#pragma unroll
        for (int e = 0; e < E_NUM; e++) if (e != i1 && p[e] > p[i2]) i2 = e;

        float denom = p[i1] + p[i2];
        float w1 = p[i1] / denom, w2 = p[i2] / denom;
        int r1 = atomicAdd(&g_cnt[i1], 1);
        int r2 = atomicAdd(&g_cnt[i2], 1);
        g_tok_exp[2 * t]     = i1; g_tok_wt[2 * t]     = w1; g_tok_rank[2 * t]     = r1;
        g_tok_exp[2 * t + 1] = i2; g_tok_wt[2 * t + 1] = w2; g_tok_rank[2 * t + 1] = r2;
        if (write_logits) {
#pragma unroll
            for (int e = 0; e < E_NUM; e++)
                logits_out[(size_t)t * E_NUM + e] = l[e];
        }
    }
}

// ---------------- grouped GEMM1: hidden = silu(x@gate) * (x@up) ----------------
// grid.x: row tiles over slots (per-expert), grid.y: I/BN column tiles
__global__ __launch_bounds__(256, 2)
void gemm1_kernel(const float* __restrict__ x,
                  const float* __restrict__ gate_w,
                  const float* __restrict__ up_w) {
    __shared__ int s_e, s_row0, s_end;
    if (threadIdx.x == 0) {
        int b = blockIdx.x, acc = 0, fe = -1, frow0 = 0, fend = 0;
        for (int e = 0; e < E_NUM; e++) {
            int cnt = g_off[e + 1] - g_off[e];
            int nt = (cnt + BM - 1) >> 6;
            if (fe < 0 && b < acc + nt) {
                fe = e; frow0 = g_off[e] + (b - acc) * BM; fend = g_off[e] + cnt;
            }
            acc += nt;
        }
        s_e = fe; s_row0 = frow0; s_end = fend;
    }
    __syncthreads();
    int e = s_e;
    if (e < 0) return;
    int row0 = s_row0, rend = s_end;
    int n0 = blockIdx.y * BN;
    int tid = threadIdx.x, warp = tid >> 5, lane = tid & 31;

    __shared__ int s_tok[BM];
    __shared__ __align__(16) float As[BK][BM];
    __shared__ __align__(16) float Bg[BK][BN];
    __shared__ __align__(16) float Bu[BK][BN];

    if (tid < BM) {
        int r = row0 + tid;
        s_tok[tid] = g_perm[(r < rend) ? r : row0];
    }
    __syncthreads();

    // load lane assignments
    int la_m = tid >> 2, la_k4 = (tid & 3) * 4;           // A: 1 float4 per thread
    int lb_r = tid >> 5, lb_c = lane * 4;                 // B: 2 float4 per thread per matrix

    const float* ax  = x + (size_t)s_tok[la_m] * H_DIM + la_k4;
    const float* bg0 = gate_w + (size_t)e * H_DIM * I_DIM + (size_t)lb_r * I_DIM + n0 + lb_c;
    const float* bu0 = up_w   + (size_t)e * H_DIM * I_DIM + (size_t)lb_r * I_DIM + n0 + lb_c;

    unsigned long long ag[8][2], au[8][2];
#pragma unroll
    for (int i = 0; i < 8; i++) { ag[i][0] = 0ull; ag[i][1] = 0ull; au[i][0] = 0ull; au[i][1] = 0ull; }

    // prefetch tile 0
    float4 ra  = *(const float4*)(ax);
    float4 rg0 = *(const float4*)(bg0);
    float4 rg1 = *(const float4*)(bg0 + 8 * I_DIM);
    float4 ru0 = *(const float4*)(bu0);
    float4 ru1 = *(const float4*)(bu0 + 8 * I_DIM);

    for (int k0 = 0; k0 < H_DIM; k0 += BK) {
        As[la_k4 + 0][la_m] = ra.x; As[la_k4 + 1][la_m] = ra.y;
        As[la_k4 + 2][la_m] = ra.z; As[la_k4 + 3][la_m] = ra.w;
        *(float4*)&Bg[lb_r][lb_c]     = rg0;
        *(float4*)&Bg[lb_r + 8][lb_c] = rg1;
        *(float4*)&Bu[lb_r][lb_c]     = ru0;
        *(float4*)&Bu[lb_r + 8][lb_c] = ru1;
        __syncthreads();

        if (k0 + BK < H_DIM) {
            ra  = *(const float4*)(ax  + k0 + BK);
            rg0 = *(const float4*)(bg0 + (size_t)(k0 + BK) * I_DIM);
            rg1 = *(const float4*)(bg0 + (size_t)(k0 + BK + 8) * I_DIM);
            ru0 = *(const float4*)(bu0 + (size_t)(k0 + BK) * I_DIM);
            ru1 = *(const float4*)(bu0 + (size_t)(k0 + BK + 8) * I_DIM);
        }

#pragma unroll
        for (int k = 0; k < BK; k++) {
            float4 a0 = *(const float4*)(&As[k][warp * 8]);
            float4 a1 = *(const float4*)(&As[k][warp * 8 + 4]);
            ulonglong2 bgv = *(const ulonglong2*)(&Bg[k][lane * 4]);
            ulonglong2 buv = *(const ulonglong2*)(&Bu[k][lane * 4]);
            float av[8] = {a0.x, a0.y, a0.z, a0.w, a1.x, a1.y, a1.z, a1.w};
#pragma unroll
            for (int i = 0; i < 8; i++) {
                unsigned long long ad;
                PACK2(ad, av[i]);
                FMA2(ag[i][0], ad, bgv.x);
                FMA2(ag[i][1], ad, bgv.y);
                FMA2(au[i][0], ad, buv.x);
                FMA2(au[i][1], ad, buv.y);
            }
        }
        __syncthreads();
    }

    int valid_m = rend - row0; if (valid_m > BM) valid_m = BM;
#pragma unroll
    for (int i = 0; i < 8; i++) {
        int m = warp * 8 + i;
        if (m < valid_m) {
            float g0, g1, g2, g3, u0, u1, u2, u3;
            UNPACK2(g0, g1, ag[i][0]); UNPACK2(g2, g3, ag[i][1]);
            UNPACK2(u0, u1, au[i][0]); UNPACK2(u2, u3, au[i][1]);
            float4 o;
            o.x = u0 * (g0 / (1.f + __expf(-g0)));
            o.y = u1 * (g1 / (1.f + __expf(-g1)));
            o.z = u2 * (g2 / (1.f + __expf(-g2)));
            o.w = u3 * (g3 / (1.f + __expf(-g3)));
            *(float4*)(g_hidden + (size_t)(row0 + m) * I_DIM + n0 + lane * 4) = o;
        }
    }
}

// ---------------- grouped GEMM2: out[tok] += w * (hidden @ out_w[e]) ----------------
__global__ __launch_bounds__(256, 2)
void gemm2_kernel(const float* __restrict__ out_w,
                  float* __restrict__ out) {
    __shared__ int s_e, s_row0, s_end;
    if (threadIdx.x == 0) {
        int b = blockIdx.x, acc = 0, fe = -1, frow0 = 0, fend = 0;
        for (int e = 0; e < E_NUM; e++) {
            int cnt = g_off[e + 1] - g_off[e];
            int nt = (cnt + BM - 1) >> 6;
            if (fe < 0 && b < acc + nt) {
                fe = e; frow0 = g_off[e] + (b - acc) * BM; fend = g_off[e] + cnt;
            }
            acc += nt;
        }
        s_e = fe; s_row0 = frow0; s_end = fend;
    }
    __syncthreads();
    int e = s_e;
    if (e < 0) return;
    int row0 = s_row0, rend = s_end;
    int n0 = blockIdx.y * BN;
    int tid = threadIdx.x, warp = tid >> 5, lane = tid & 31;

    __shared__ int   s_tok[BM];
    __shared__ float s_wt[BM];
    __shared__ __align__(16) float As[BK][BM];
    __shared__ __align__(16) float Bs[BK][BN];

    if (tid < BM) {
        int r = row0 + tid;
        int rr = (r < rend) ? r : row0;
        s_tok[tid] = g_perm[rr];
        s_wt[tid]  = g_pwt[rr];
    }
    __syncthreads();

    int la_m = tid >> 2, la_k4 = (tid & 3) * 4;
    int lb_r = tid >> 5, lb_c = lane * 4;

    int arow = row0 + la_m; if (arow >= rend) arow = row0;
    const float* ax = g_hidden + (size_t)arow * I_DIM + la_k4;
    const float* b0 = out_w + (size_t)e * I_DIM * H_DIM + (size_t)lb_r * H_DIM + n0 + lb_c;

    unsigned long long ac[8][2];
#pragma unroll
    for (int i = 0; i < 8; i++) { ac[i][0] = 0ull; ac[i][1] = 0ull; }

    float4 ra  = *(const float4*)(ax);
    float4 rb0 = *(const float4*)(b0);
    float4 rb1 = *(const float4*)(b0 + 8 * H_DIM);

    for (int k0 = 0; k0 < I_DIM; k0 += BK) {
        As[la_k4 + 0][la_m] = ra.x; As[la_k4 + 1][la_m] = ra.y;
        As[la_k4 + 2][la_m] = ra.z; As[la_k4 + 3][la_m] = ra.w;
        *(float4*)&Bs[lb_r][lb_c]     = rb0;
        *(float4*)&Bs[lb_r + 8][lb_c] = rb1;
        __syncthreads();

        if (k0 + BK < I_DIM) {
            ra  = *(const float4*)(ax + k0 + BK);
            rb0 = *(const float4*)(b0 + (size_t)(k0 + BK) * H_DIM);
            rb1 = *(const float4*)(b0 + (size_t)(k0 + BK + 8) * H_DIM);
        }

#pragma unroll
        for (int k = 0; k < BK; k++) {
            float4 a0 = *(const float4*)(&As[k][warp * 8]);
            float4 a1 = *(const float4*)(&As[k][warp * 8 + 4]);
            ulonglong2 bv = *(const ulonglong2*)(&Bs[k][lane * 4]);
            float av[8] = {a0.x, a0.y, a0.z, a0.w, a1.x, a1.y, a1.z, a1.w};
#pragma unroll
            for (int i = 0; i < 8; i++) {
                unsigned long long ad;
                PACK2(ad, av[i]);
                FMA2(ac[i][0], ad, bv.x);
                FMA2(ac[i][1], ad, bv.y);
            }
        }
        __syncthreads();
    }

    int valid_m = rend - row0; if (valid_m > BM) valid_m = BM;
#pragma unroll
    for (int i = 0; i < 8; i++) {
        int m = warp * 8 + i;
        if (m < valid_m) {
            float w = s_wt[m];
            float* op = out + (size_t)s_tok[m] * H_DIM + n0 + lane * 4;
            float o0, o1, o2, o3;
            UNPACK2(o0, o1, ac[i][0]); UNPACK2(o2, o3, ac[i][1]);
            atomicAdd(op + 0, o0 * w);
            atomicAdd(op + 1, o1 * w);
            atomicAdd(op + 2, o2 * w);
            atomicAdd(op + 3, o3 * w);
        }
    }
}

// ---------------- launcher ----------------
extern "C" void kernel_launch(void* const* d_in, const int* in_sizes, int n_in,
                              void* d_out, int out_size) {
    const float* x  = (const float*)d_in[0];   // hidden_states [B,S,H]
    const float* rw = (const float*)d_in[1];   // router_w [H,E]
    const float* gw = (const float*)d_in[2];   // gate_w [E,H,I]
    const float* uw = (const float*)d_in[3];   // up_w   [E,H,I]
    const float* ow = (const float*)d_in[4];   // out_w  [E,I,H]
    float* out = (float*)d_out;

    int write_logits = (out_size >= T_TOK * H_DIM + T_TOK * E_NUM) ? 1 : 0;
    float* logits = out + (size_t)T_TOK * H_DIM;

    cudaMemsetAsync(out, 0, (size_t)T_TOK * H_DIM * sizeof(float), 0);
    zero_cnt_kernel<<<1, 32>>>();
    router_kernel<<<T_TOK, 256>>>(x, rw, logits, write_logits);
    scan_off_kernel<<<1, 32>>>();
    build_perm_kernel<<<(NSLOT + 255) / 256, 256>>>();
    gemm1_kernel<<<dim3(MAX_ROW_TILES, I_DIM / BN), 256>>>(x, gw, uw);
    gemm2_kernel<<<dim3(MAX_ROW_TILES, H_DIM / BN), 256>>>(ow, out);
}

// round 11
// speedup vs baseline: 3.2465x; 3.2465x over previous
#include <cuda_runtime.h>
#include <cuda_fp16.h>
#include <cstdint>
#include <math.h>

// ---------------- problem constants ----------------
#define T_TOK   4096
#define H_DIM   1024
#define I_DIM   2048
#define E_NUM   8
#define NSLOT   (T_TOK * 2)
#define ROW_TILES 71          // sum ceil(cnt_e/128) <= 64 + 7

#define BKH   32              // K halfs per stage
#define RSTRB 80              // padded row stride bytes (40 halfs) - conflict-free ldmatrix
#define TILE0 1152            // tile region start in dynamic smem

#define G1_STAGE_B (3 * 128 * RSTRB)   // A + Bg + Bu = 30720
#define G1_SMEM    (TILE0 + 2 * G1_STAGE_B)
#define G2_STAGE_B (2 * 128 * RSTRB)   // A + B = 20480
#define G2_SMEM    (TILE0 + 2 * G2_STAGE_B)

// ---------------- device scratch ----------------
__device__ int   g_cnt[E_NUM];
__device__ int   g_off[E_NUM + 1];
__device__ int   g_tok_exp[NSLOT];
__device__ float g_tok_wt[NSLOT];
__device__ int   g_tok_rank[NSLOT];
__device__ int   g_perm[NSLOT];
__device__ float g_pwt[NSLOT];

__device__ __half g_xh [(size_t)T_TOK * H_DIM];                 // x fp16 [t][k]
__device__ __half g_wg [(size_t)E_NUM * I_DIM * H_DIM];        // gate K-major [e][n][k]
__device__ __half g_wu [(size_t)E_NUM * I_DIM * H_DIM];        // up   K-major
__device__ __half g_w2 [(size_t)E_NUM * H_DIM * I_DIM];        // down K-major [e][n in H][k in I]
__device__ __half g_hid[(size_t)(NSLOT + 128) * I_DIM];        // hidden fp16 (pad rows stay 0)

// ---------------- PTX helpers (all legal at plain sm_103) ----------------
__device__ __forceinline__ uint32_t smem_u32(const void* p) {
    uint32_t a;
    asm("{ .reg .u64 t; cvta.to.shared.u64 t, %1; cvt.u32.u64 %0, t; }" : "=r"(a) : "l"(p));
    return a;
}
#define CPA16(dst, src) \
    asm volatile("cp.async.cg.shared.global [%0], [%1], 16;" :: "r"(dst), "l"(src))
#define CPCOMMIT() asm volatile("cp.async.commit_group;" ::: "memory")
#define CPWAIT1()  asm volatile("cp.async.wait_group 1;" ::: "memory")

#define LDM4(r, addr) \
    asm volatile("ldmatrix.sync.aligned.m8n8.x4.shared.b16 {%0,%1,%2,%3}, [%4];" \
        : "=r"((r)[0]), "=r"((r)[1]), "=r"((r)[2]), "=r"((r)[3]) : "r"(addr))

#define MMA16816(c, a, b0v, b1v) \
    asm volatile("mma.sync.aligned.m16n8k16.row.col.f32.f16.f16.f32 " \
        "{%0,%1,%2,%3}, {%4,%5,%6,%7}, {%8,%9}, {%0,%1,%2,%3};" \
        : "+f"((c)[0]), "+f"((c)[1]), "+f"((c)[2]), "+f"((c)[3]) \
        : "r"((a)[0]), "r"((a)[1]), "r"((a)[2]), "r"((a)[3]), "r"(b0v), "r"(b1v))

// ---------------- routing kernels (proven) ----------------
__global__ void zero_cnt_kernel() {
    if (threadIdx.x < E_NUM) g_cnt[threadIdx.x] = 0;
}
__global__ void scan_off_kernel() {
    if (threadIdx.x == 0) {
        int a = 0;
        for (int e = 0; e < E_NUM; e++) { g_off[e] = a; a += g_cnt[e]; }
        g_off[E_NUM] = a;
    }
}
__global__ void build_perm_kernel() {
    int idx = blockIdx.x * blockDim.x + threadIdx.x;
    if (idx < NSLOT) {
        int e = g_tok_exp[idx];
        int slot = g_off[e] + g_tok_rank[idx];
        g_perm[slot] = idx >> 1;
        g_pwt[slot]  = g_tok_wt[idx];
    }
}
__global__ void router_kernel(const float* __restrict__ x,
                              const float* __restrict__ rw,
                              float* __restrict__ logits_out,
                              int write_logits) {
    int t = blockIdx.x;
    int warp = threadIdx.x >> 5, lane = threadIdx.x & 31;
    const float* xr = x + (size_t)t * H_DIM;
    float s = 0.f;
    for (int h = lane; h < H_DIM; h += 32)
        s += xr[h] * rw[h * E_NUM + warp];
#pragma unroll
    for (int o = 16; o; o >>= 1) s += __shfl_xor_sync(0xffffffffu, s, o);
    __shared__ float lg[E_NUM];
    if (lane == 0) lg[warp] = s;
    __syncthreads();
    if (threadIdx.x == 0) {
        float l[E_NUM], mx = -1e30f;
#pragma unroll
        for (int e = 0; e < E_NUM; e++) { l[e] = lg[e]; mx = fmaxf(mx, l[e]); }
        float p[E_NUM], sum = 0.f;
#pragma unroll
        for (int e = 0; e < E_NUM; e++) { p[e] = expf(l[e] - mx); sum += p[e]; }
#pragma unroll
        for (int e = 0; e < E_NUM; e++) p[e] /= sum;
        int i1 = 0;
#pragma unroll
        for (int e = 1; e < E_NUM; e++) if (p[e] > p[i1]) i1 = e;
        int i2 = (i1 == 0) ? 1 : 0;
#pragma unroll
        for (int e = 0; e < E_NUM; e++) if (e != i1 && p[e] > p[i2]) i2 = e;
        float denom = p[i1] + p[i2];
        int r1 = atomicAdd(&g_cnt[i1], 1);
        int r2 = atomicAdd(&g_cnt[i2], 1);
        g_tok_exp[2 * t]     = i1; g_tok_wt[2 * t]     = p[i1] / denom; g_tok_rank[2 * t]     = r1;
        g_tok_exp[2 * t + 1] = i2; g_tok_wt[2 * t + 1] = p[i2] / denom; g_tok_rank[2 * t + 1] = r2;
        if (write_logits) {
#pragma unroll
            for (int e = 0; e < E_NUM; e++)
                logits_out[(size_t)t * E_NUM + e] = l[e];
        }
    }
}

// ---------------- conversion kernels ----------------
__global__ void conv_x_kernel(const float* __restrict__ x) {
    int t = blockIdx.x;
    int c = threadIdx.x * 4;
    float4 v = *(const float4*)(x + (size_t)t * H_DIM + c);
    __half2 a = __floats2half2_rn(v.x, v.y);
    __half2 b = __floats2half2_rn(v.z, v.w);
    *(uint2*)(g_xh + (size_t)t * H_DIM + c) = make_uint2(
        *(uint32_t*)&a, *(uint32_t*)&b);
}

// transpose: src [E][K][N] fp32 -> dst [E][N][K] fp16
__global__ void conv_wT_kernel(const float* __restrict__ src, int which, int K, int N) {
    __half* dst = (which == 0) ? g_wg : (which == 1) ? g_wu : g_w2;
    int e = blockIdx.z;
    const float* s = src + (size_t)e * K * N;
    __half* d = dst + (size_t)e * N * K;
    int n0 = blockIdx.x * 32, k0 = blockIdx.y * 32;
    int tx = threadIdx.x, ty = threadIdx.y;
    __shared__ float tl[32][33];
#pragma unroll
    for (int j = 0; j < 4; j++)
        tl[ty + 8 * j][tx] = s[(size_t)(k0 + ty + 8 * j) * N + n0 + tx];
    __syncthreads();
#pragma unroll
    for (int j = 0; j < 4; j++) {
        int n = n0 + ty + 8 * j;
        int k = k0 + tx;
        d[(size_t)n * K + k] = __float2half(tl[tx][ty + 8 * j]);
    }
}

// ---------------- tile resolver ----------------
__device__ __forceinline__ void resolve_tile(int* hdr) {
    if (threadIdx.x == 0) {
        int b = blockIdx.x, acc = 0, fe = -1, fr = 0, fn = 0;
        for (int e = 0; e < E_NUM; e++) {
            int c = g_off[e + 1] - g_off[e];
            int nt = (c + 127) >> 7;
            if (fe < 0 && b < acc + nt) { fe = e; fr = g_off[e] + (b - acc) * 128; fn = g_off[e] + c; }
            acc += nt;
        }
        hdr[0] = fe; hdr[1] = fr; hdr[2] = fn;
    }
}

// ---------------- GEMM1: hidden = silu(x@gate)*(x@up), fp16 HMMA ----------------
__global__ void __launch_bounds__(256)
gemm1_mma() {
    extern __shared__ char dsm[];
    int tid = threadIdx.x, warp = tid >> 5, lane = tid & 31;
    int* hdr = (int*)dsm;
    int* s_tok = (int*)(dsm + 64);
    resolve_tile(hdr);
    __syncthreads();
    int e = hdr[0];
    if (e < 0) return;
    int row0 = hdr[1], rend = hdr[2];
    int n0 = blockIdx.y * 128;
    if (tid < 128) {
        int r = row0 + tid;
        s_tok[tid] = g_perm[(r < rend) ? r : row0];
    }
    __syncthreads();
    uint32_t sb = smem_u32(dsm);

    // per-thread load lanes: row = tid>>1, two 16B segs
    int lrow = tid >> 1, seg0 = (tid & 1) * 2;
    const char* aP = (const char*)(g_xh + (size_t)s_tok[lrow] * H_DIM) + seg0 * 16;
    const char* gP = (const char*)(g_wg + ((size_t)e * I_DIM + n0 + lrow) * H_DIM) + seg0 * 16;
    const char* uP = (const char*)(g_wu + ((size_t)e * I_DIM + n0 + lrow) * H_DIM) + seg0 * 16;
    uint32_t dstBase = sb + TILE0 + lrow * RSTRB + seg0 * 16;

#define G1LOAD(s, k0) { \
        uint32_t d = dstBase + (s) * G1_STAGE_B; int kb = (k0) * 2; \
        CPA16(d,             aP + kb); CPA16(d + 16,          aP + kb + 16); \
        CPA16(d + 10240,     gP + kb); CPA16(d + 10240 + 16,  gP + kb + 16); \
        CPA16(d + 20480,     uP + kb); CPA16(d + 20480 + 16,  uP + kb + 16); }

    float cg[2][8][4], cu[2][8][4];
#pragma unroll
    for (int i = 0; i < 2; i++)
#pragma unroll
        for (int j = 0; j < 8; j++)
#pragma unroll
            for (int q = 0; q < 4; q++) { cg[i][j][q] = 0.f; cu[i][j][q] = 0.f; }

    G1LOAD(0, 0); CPCOMMIT();
    G1LOAD(1, BKH); CPCOMMIT();

    int wm = warp & 3, wn = warp >> 2;                  // 4m x 2n warps
    uint32_t aOff = TILE0 + (wm * 32 + (lane & 15)) * RSTRB + ((lane >> 4) & 1) * 16;
    uint32_t bOff = TILE0 + 10240 + (wn * 64 + (lane & 15)) * RSTRB + ((lane >> 4) & 1) * 16;

    const int NS = H_DIM / BKH;   // 32 stages
    for (int s = 0; s < NS; s++) {
        CPWAIT1();
        __syncthreads();
        int p = s & 1;
        uint32_t bA = sb + aOff + p * G1_STAGE_B;
        uint32_t bB = sb + bOff + p * G1_STAGE_B;
#pragma unroll
        for (int k16 = 0; k16 < 2; k16++) {
            uint32_t a0[4], a1[4];
            LDM4(a0, bA + k16 * 32);
            LDM4(a1, bA + 16 * RSTRB + k16 * 32);
#pragma unroll
            for (int q = 0; q < 4; q++) {
                uint32_t bg[4], bu[4];
                LDM4(bg, bB + q * 16 * RSTRB + k16 * 32);
                LDM4(bu, bB + 10240 + q * 16 * RSTRB + k16 * 32);
                MMA16816(cg[0][2 * q],     a0, bg[0], bg[2]);
                MMA16816(cg[0][2 * q + 1], a0, bg[1], bg[3]);
                MMA16816(cg[1][2 * q],     a1, bg[0], bg[2]);
                MMA16816(cg[1][2 * q + 1], a1, bg[1], bg[3]);
                MMA16816(cu[0][2 * q],     a0, bu[0], bu[2]);
                MMA16816(cu[0][2 * q + 1], a0, bu[1], bu[3]);
                MMA16816(cu[1][2 * q],     a1, bu[0], bu[2]);
                MMA16816(cu[1][2 * q + 1], a1, bu[1], bu[3]);
            }
        }
        __syncthreads();
        if (s + 2 < NS) { G1LOAD(s & 1, (s + 2) * BKH); }
        CPCOMMIT();
    }
#undef G1LOAD

    // epilogue: silu(g)*u -> fp16 hidden
    int rA = wm * 32 + (lane >> 2);
    int cBase = n0 + wn * 64 + 2 * (lane & 3);
#pragma unroll
    for (int mt = 0; mt < 2; mt++) {
#pragma unroll
        for (int nt = 0; nt < 8; nt++) {
            int col = cBase + nt * 8;
            int r0r = rA + mt * 16;
            float* g0 = cg[mt][nt];
            float* u0 = cu[mt][nt];
            if (row0 + r0r < rend) {
                float h0 = u0[0] * (g0[0] / (1.f + __expf(-g0[0])));
                float h1 = u0[1] * (g0[1] / (1.f + __expf(-g0[1])));
                __half2 hv = __floats2half2_rn(h0, h1);
                *(__half2*)(g_hid + (size_t)(row0 + r0r) * I_DIM + col) = hv;
            }
            if (row0 + r0r + 8 < rend) {
                float h2 = u0[2] * (g0[2] / (1.f + __expf(-g0[2])));
                float h3 = u0[3] * (g0[3] / (1.f + __expf(-g0[3])));
                __half2 hv = __floats2half2_rn(h2, h3);
                *(__half2*)(g_hid + (size_t)(row0 + r0r + 8) * I_DIM + col) = hv;
            }
        }
    }
}

// ---------------- GEMM2: out[tok] += wt * (hidden @ down), fp16 HMMA ----------------
__global__ void __launch_bounds__(256)
gemm2_mma(float* __restrict__ out) {
    extern __shared__ char dsm[];
    int tid = threadIdx.x, warp = tid >> 5, lane = tid & 31;
    int* hdr = (int*)dsm;
    int* s_tok = (int*)(dsm + 64);
    float* s_wt = (float*)(dsm + 576);
    resolve_tile(hdr);
    __syncthreads();
    int e = hdr[0];
    if (e < 0) return;
    int row0 = hdr[1], rend = hdr[2];
    int n0 = blockIdx.y * 128;
    if (tid < 128) {
        int r = row0 + tid;
        int rr = (r < rend) ? r : row0;
        s_tok[tid] = g_perm[rr];
        s_wt[tid]  = g_pwt[rr];
    }
    __syncthreads();
    uint32_t sb = smem_u32(dsm);

    int lrow = tid >> 1, seg0 = (tid & 1) * 2;
    const char* aP = (const char*)(g_hid + (size_t)(row0 + lrow) * I_DIM) + seg0 * 16;
    const char* bP = (const char*)(g_w2 + ((size_t)e * H_DIM + n0 + lrow) * I_DIM) + seg0 * 16;
    uint32_t dstBase = sb + TILE0 + lrow * RSTRB + seg0 * 16;

#define G2LOAD(s, k0) { \
        uint32_t d = dstBase + (s) * G2_STAGE_B; int kb = (k0) * 2; \
        CPA16(d,            aP + kb); CPA16(d + 16,         aP + kb + 16); \
        CPA16(d + 10240,    bP + kb); CPA16(d + 10240 + 16, bP + kb + 16); }

    float cc[2][8][4];
#pragma unroll
    for (int i = 0; i < 2; i++)
#pragma unroll
        for (int j = 0; j < 8; j++)
#pragma unroll
            for (int q = 0; q < 4; q++) cc[i][j][q] = 0.f;

    G2LOAD(0, 0); CPCOMMIT();
    G2LOAD(1, BKH); CPCOMMIT();

    int wm = warp & 3, wn = warp >> 2;
    uint32_t aOff = TILE0 + (wm * 32 + (lane & 15)) * RSTRB + ((lane >> 4) & 1) * 16;
    uint32_t bOff = TILE0 + 10240 + (wn * 64 + (lane & 15)) * RSTRB + ((lane >> 4) & 1) * 16;

    const int NS = I_DIM / BKH;   // 64 stages
    for (int s = 0; s < NS; s++) {
        CPWAIT1();
        __syncthreads();
        int p = s & 1;
        uint32_t bA = sb + aOff + p * G2_STAGE_B;
        uint32_t bB = sb + bOff + p * G2_STAGE_B;
#pragma unroll
        for (int k16 = 0; k16 < 2; k16++) {
            uint32_t a0[4], a1[4];
            LDM4(a0, bA + k16 * 32);
            LDM4(a1, bA + 16 * RSTRB + k16 * 32);
#pragma unroll
            for (int q = 0; q < 4; q++) {
                uint32_t bb[4];
                LDM4(bb, bB + q * 16 * RSTRB + k16 * 32);
                MMA16816(cc[0][2 * q],     a0, bb[0], bb[2]);
                MMA16816(cc[0][2 * q + 1], a0, bb[1], bb[3]);
                MMA16816(cc[1][2 * q],     a1, bb[0], bb[2]);
                MMA16816(cc[1][2 * q + 1], a1, bb[1], bb[3]);
            }
        }
        __syncthreads();
        if (s + 2 < NS) { G2LOAD(s & 1, (s + 2) * BKH); }
        CPCOMMIT();
    }
#undef G2LOAD

    int rA = wm * 32 + (lane >> 2);
    int cBase = n0 + wn * 64 + 2 * (lane & 3);
#pragma unroll
    for (int mt = 0; mt < 2; mt++) {
#pragma unroll
        for (int nt = 0; nt < 8; nt++) {
            int col = cBase + nt * 8;
            int r0r = rA + mt * 16;
            float* c0 = cc[mt][nt];
            if (row0 + r0r < rend) {
                float w = s_wt[r0r];
                float* op = out + (size_t)s_tok[r0r] * H_DIM + col;
                atomicAdd(op + 0, c0[0] * w);
                atomicAdd(op + 1, c0[1] * w);
            }
            if (row0 + r0r + 8 < rend) {
                float w = s_wt[r0r + 8];
                float* op = out + (size_t)s_tok[r0r + 8] * H_DIM + col;
                atomicAdd(op + 0, c0[2] * w);
                atomicAdd(op + 1, c0[3] * w);
            }
        }
    }
}

// ---------------- launcher ----------------
extern "C" void kernel_launch(void* const* d_in, const int* in_sizes, int n_in,
                              void* d_out, int out_size) {
    const float* x  = (const float*)d_in[0];   // [B,S,H]
    const float* rw = (const float*)d_in[1];   // [H,E]
    const float* gw = (const float*)d_in[2];   // [E,H,I]
    const float* uw = (const float*)d_in[3];   // [E,H,I]
    const float* ow = (const float*)d_in[4];   // [E,I,H]
    float* out = (float*)d_out;

    (void)cudaFuncSetAttribute(gemm1_mma, cudaFuncAttributeMaxDynamicSharedMemorySize, G1_SMEM);
    (void)cudaFuncSetAttribute(gemm2_mma, cudaFuncAttributeMaxDynamicSharedMemorySize, G2_SMEM);

    int write_logits = (out_size >= T_TOK * H_DIM + T_TOK * E_NUM) ? 1 : 0;
    float* logits = out + (size_t)T_TOK * H_DIM;

    cudaMemsetAsync(out, 0, (size_t)T_TOK * H_DIM * sizeof(float), 0);
    zero_cnt_kernel<<<1, 32>>>();
    router_kernel<<<T_TOK, 256>>>(x, rw, logits, write_logits);
    scan_off_kernel<<<1, 32>>>();
    build_perm_kernel<<<(NSLOT + 255) / 256, 256>>>();

    conv_x_kernel<<<T_TOK, 256>>>(x);
    conv_wT_kernel<<<dim3(I_DIM / 32, H_DIM / 32, E_NUM), dim3(32, 8)>>>(gw, 0, H_DIM, I_DIM);
    conv_wT_kernel<<<dim3(I_DIM / 32, H_DIM / 32, E_NUM), dim3(32, 8)>>>(uw, 1, H_DIM, I_DIM);
    conv_wT_kernel<<<dim3(H_DIM / 32, I_DIM / 32, E_NUM), dim3(32, 8)>>>(ow, 2, I_DIM, H_DIM);

    gemm1_mma<<<dim3(ROW_TILES, I_DIM / 128), 256, G1_SMEM>>>();
    gemm2_mma<<<dim3(ROW_TILES, H_DIM / 128), 256, G2_SMEM>>>(out);
}

// round 13
// speedup vs baseline: 3.2915x; 1.0138x over previous
#include <cuda_runtime.h>
#include <cuda_fp16.h>
#include <cstdint>
#include <math.h>

// ---------------- problem constants ----------------
#define T_TOK   4096
#define H_DIM   1024
#define I_DIM   2048
#define E_NUM   8
#define NSLOT   (T_TOK * 2)
#define ROW_TILES 71          // sum ceil(cnt_e/128) <= 64 + 7

#define BKH   32              // K halfs per stage
#define RSTRB 80              // padded row stride bytes (40 halfs) - conflict-free ldmatrix
#define TILE0 1152            // tile region start in dynamic smem
#define NSTG  3               // pipeline stages

#define G1_STAGE_B (3 * 128 * RSTRB)   // A + Bg + Bu = 30720
#define G1_SMEM    (TILE0 + NSTG * G1_STAGE_B)
#define G2_STAGE_B (2 * 128 * RSTRB)   // A + B = 20480
#define G2_SMEM    (TILE0 + NSTG * G2_STAGE_B)

// ---------------- device scratch ----------------
__device__ int   g_cnt[E_NUM];
__device__ int   g_off[E_NUM + 1];
__device__ int   g_tok_exp[NSLOT];
__device__ float g_tok_wt[NSLOT];
__device__ int   g_tok_rank[NSLOT];
__device__ int   g_perm[NSLOT];
__device__ float g_pwt[NSLOT];
__device__ int   g_slot_of[NSLOT];                             // assignment idx -> slot

__device__ __half g_xh [(size_t)T_TOK * H_DIM];                // x fp16 [t][k]
__device__ __half g_wg [(size_t)E_NUM * I_DIM * H_DIM];        // gate K-major [e][n][k]
__device__ __half g_wu [(size_t)E_NUM * I_DIM * H_DIM];        // up   K-major
__device__ __half g_w2 [(size_t)E_NUM * H_DIM * I_DIM];        // down K-major [e][n in H][k in I]
__device__ __half g_hid[(size_t)(NSLOT + 128) * I_DIM];        // hidden fp16
__device__ float  g_y  [(size_t)(NSLOT + 128) * H_DIM];        // per-slot down output fp32

// ---------------- PTX helpers (legal at plain sm_103) ----------------
__device__ __forceinline__ uint32_t smem_u32(const void* p) {
    uint32_t a;
    asm("{ .reg .u64 t; cvta.to.shared.u64 t, %1; cvt.u32.u64 %0, t; }" : "=r"(a) : "l"(p));
    return a;
}
#define CPA16(dst, src) \
    asm volatile("cp.async.cg.shared.global [%0], [%1], 16;" :: "r"(dst), "l"(src))
#define CPCOMMIT() asm volatile("cp.async.commit_group;" ::: "memory")
#define CPWAIT1()  asm volatile("cp.async.wait_group 1;" ::: "memory")

#define LDM4(r, addr) \
    asm volatile("ldmatrix.sync.aligned.m8n8.x4.shared.b16 {%0,%1,%2,%3}, [%4];" \
        : "=r"((r)[0]), "=r"((r)[1]), "=r"((r)[2]), "=r"((r)[3]) : "r"(addr))

#define MMA16816(c, a, b0v, b1v) \
    asm volatile("mma.sync.aligned.m16n8k16.row.col.f32.f16.f16.f32 " \
        "{%0,%1,%2,%3}, {%4,%5,%6,%7}, {%8,%9}, {%0,%1,%2,%3};" \
        : "+f"((c)[0]), "+f"((c)[1]), "+f"((c)[2]), "+f"((c)[3]) \
        : "r"((a)[0]), "r"((a)[1]), "r"((a)[2]), "r"((a)[3]), "r"(b0v), "r"(b1v))

// ---------------- routing kernels ----------------
__global__ void zero_cnt_kernel() {
    if (threadIdx.x < E_NUM) g_cnt[threadIdx.x] = 0;
}
__global__ void scan_off_kernel() {
    if (threadIdx.x == 0) {
        int a = 0;
        for (int e = 0; e < E_NUM; e++) { g_off[e] = a; a += g_cnt[e]; }
        g_off[E_NUM] = a;
    }
}
__global__ void build_perm_kernel() {
    int idx = blockIdx.x * blockDim.x + threadIdx.x;
    if (idx < NSLOT) {
        int e = g_tok_exp[idx];
        int slot = g_off[e] + g_tok_rank[idx];
        g_perm[slot] = idx >> 1;
        g_pwt[slot]  = g_tok_wt[idx];
        g_slot_of[idx] = slot;
    }
}
__global__ void router_kernel(const float* __restrict__ x,
                              const float* __restrict__ rw,
                              float* __restrict__ logits_out,
                              int write_logits) {
    int t = blockIdx.x;
    int warp = threadIdx.x >> 5, lane = threadIdx.x & 31;
    const float* xr = x + (size_t)t * H_DIM;
    float s = 0.f;
    for (int h = lane; h < H_DIM; h += 32)
        s += xr[h] * rw[h * E_NUM + warp];
#pragma unroll
    for (int o = 16; o; o >>= 1) s += __shfl_xor_sync(0xffffffffu, s, o);
    __shared__ float lg[E_NUM];
    if (lane == 0) lg[warp] = s;
    __syncthreads();
    if (threadIdx.x == 0) {
        float l[E_NUM], mx = -1e30f;
#pragma unroll
        for (int e = 0; e < E_NUM; e++) { l[e] = lg[e]; mx = fmaxf(mx, l[e]); }
        float p[E_NUM], sum = 0.f;
#pragma unroll
        for (int e = 0; e < E_NUM; e++) { p[e] = expf(l[e] - mx); sum += p[e]; }
#pragma unroll
        for (int e = 0; e < E_NUM; e++) p[e] /= sum;
        int i1 = 0;
#pragma unroll
        for (int e = 1; e < E_NUM; e++) if (p[e] > p[i1]) i1 = e;
        int i2 = (i1 == 0) ? 1 : 0;
#pragma unroll
        for (int e = 0; e < E_NUM; e++) if (e != i1 && p[e] > p[i2]) i2 = e;
        float denom = p[i1] + p[i2];
        int r1 = atomicAdd(&g_cnt[i1], 1);
        int r2 = atomicAdd(&g_cnt[i2], 1);
        g_tok_exp[2 * t]     = i1; g_tok_wt[2 * t]     = p[i1] / denom; g_tok_rank[2 * t]     = r1;
        g_tok_exp[2 * t + 1] = i2; g_tok_wt[2 * t + 1] = p[i2] / denom; g_tok_rank[2 * t + 1] = r2;
        if (write_logits) {
#pragma unroll
            for (int e = 0; e < E_NUM; e++)
                logits_out[(size_t)t * E_NUM + e] = l[e];
        }
    }
}

// ---------------- conversion kernels ----------------
__global__ void conv_x_kernel(const float* __restrict__ x) {
    int t = blockIdx.x;
    int c = threadIdx.x * 4;
    float4 v = *(const float4*)(x + (size_t)t * H_DIM + c);
    __half2 a = __floats2half2_rn(v.x, v.y);
    __half2 b = __floats2half2_rn(v.z, v.w);
    *(uint2*)(g_xh + (size_t)t * H_DIM + c) = make_uint2(
        *(uint32_t*)&a, *(uint32_t*)&b);
}

// transpose: src [E][K][N] fp32 -> dst [E][N][K] fp16
__global__ void conv_wT_kernel(const float* __restrict__ src, int which, int K, int N) {
    __half* dst = (which == 0) ? g_wg : (which == 1) ? g_wu : g_w2;
    int e = blockIdx.z;
    const float* s = src + (size_t)e * K * N;
    __half* d = dst + (size_t)e * N * K;
    int n0 = blockIdx.x * 32, k0 = blockIdx.y * 32;
    int tx = threadIdx.x, ty = threadIdx.y;
    __shared__ float tl[32][33];
#pragma unroll
    for (int j = 0; j < 4; j++)
        tl[ty + 8 * j][tx] = s[(size_t)(k0 + ty + 8 * j) * N + n0 + tx];
    __syncthreads();
#pragma unroll
    for (int j = 0; j < 4; j++) {
        int n = n0 + ty + 8 * j;
        int k = k0 + tx;
        d[(size_t)n * K + k] = __float2half(tl[tx][ty + 8 * j]);
    }
}

// ---------------- tile resolver ----------------
__device__ __forceinline__ void resolve_tile(int* hdr) {
    if (threadIdx.x == 0) {
        int b = blockIdx.x, acc = 0, fe = -1, fr = 0, fn = 0;
        for (int e = 0; e < E_NUM; e++) {
            int c = g_off[e + 1] - g_off[e];
            int nt = (c + 127) >> 7;
            if (fe < 0 && b < acc + nt) { fe = e; fr = g_off[e] + (b - acc) * 128; fn = g_off[e] + c; }
            acc += nt;
        }
        hdr[0] = fe; hdr[1] = fr; hdr[2] = fn;
    }
}

// ---------------- GEMM1: hidden = silu(x@gate)*(x@up), fp16 HMMA ----------------
__global__ void __launch_bounds__(256)
gemm1_mma() {
    extern __shared__ char dsm[];
    int tid = threadIdx.x, warp = tid >> 5, lane = tid & 31;
    int* hdr = (int*)dsm;
    int* s_tok = (int*)(dsm + 64);
    resolve_tile(hdr);
    __syncthreads();
    int e = hdr[0];
    if (e < 0) return;
    int row0 = hdr[1], rend = hdr[2];
    int n0 = blockIdx.y * 128;
    if (tid < 128) {
        int r = row0 + tid;
        s_tok[tid] = g_perm[(r < rend) ? r : row0];
    }
    __syncthreads();
    uint32_t sb = smem_u32(dsm);

    int lrow = tid >> 1, seg0 = (tid & 1) * 2;
    const char* aP = (const char*)(g_xh + (size_t)s_tok[lrow] * H_DIM) + seg0 * 16;
    const char* gP = (const char*)(g_wg + ((size_t)e * I_DIM + n0 + lrow) * H_DIM) + seg0 * 16;
    const char* uP = (const char*)(g_wu + ((size_t)e * I_DIM + n0 + lrow) * H_DIM) + seg0 * 16;
    uint32_t dstBase = sb + TILE0 + lrow * RSTRB + seg0 * 16;

#define G1LOAD(bufo, k0) { \
        uint32_t d = dstBase + (bufo); int kb = (k0) * 2; \
        CPA16(d,             aP + kb); CPA16(d + 16,          aP + kb + 16); \
        CPA16(d + 10240,     gP + kb); CPA16(d + 10240 + 16,  gP + kb + 16); \
        CPA16(d + 20480,     uP + kb); CPA16(d + 20480 + 16,  uP + kb + 16); }

    float cg[2][8][4], cu[2][8][4];
#pragma unroll
    for (int i = 0; i < 2; i++)
#pragma unroll
        for (int j = 0; j < 8; j++)
#pragma unroll
            for (int q = 0; q < 4; q++) { cg[i][j][q] = 0.f; cu[i][j][q] = 0.f; }

    G1LOAD(0, 0); CPCOMMIT();
    G1LOAD(G1_STAGE_B, BKH); CPCOMMIT();

    int wm = warp & 3, wn = warp >> 2;                  // 4m x 2n warps
    uint32_t aOff = TILE0 + (wm * 32 + (lane & 15)) * RSTRB + ((lane >> 4) & 1) * 16;
    uint32_t bOff = TILE0 + 10240 + (wn * 64 + (lane & 15)) * RSTRB + ((lane >> 4) & 1) * 16;

    const int NS = H_DIM / BKH;   // 32 stages
    int cOff = 0, wOff = 2 * G1_STAGE_B;   // byte offsets of compute / write buffers
    for (int s = 0; s < NS; s++) {
        CPWAIT1();
        __syncthreads();
        // issue stage s+2 loads into the ring slot last read at stage s-1
        if (s + 2 < NS) { G1LOAD(wOff, (s + 2) * BKH); }
        CPCOMMIT();
        uint32_t bA = sb + aOff + cOff;
        uint32_t bB = sb + bOff + cOff;
#pragma unroll
        for (int k16 = 0; k16 < 2; k16++) {
            uint32_t a0[4], a1[4];
            LDM4(a0, bA + k16 * 32);
            LDM4(a1, bA + 16 * RSTRB + k16 * 32);
#pragma unroll
            for (int q = 0; q < 4; q++) {
                uint32_t bg[4], bu[4];
                LDM4(bg, bB + q * 16 * RSTRB + k16 * 32);
                LDM4(bu, bB + 10240 + q * 16 * RSTRB + k16 * 32);
                MMA16816(cg[0][2 * q],     a0, bg[0], bg[2]);
                MMA16816(cg[0][2 * q + 1], a0, bg[1], bg[3]);
                MMA16816(cg[1][2 * q],     a1, bg[0], bg[2]);
                MMA16816(cg[1][2 * q + 1], a1, bg[1], bg[3]);
                MMA16816(cu[0][2 * q],     a0, bu[0], bu[2]);
                MMA16816(cu[0][2 * q + 1], a0, bu[1], bu[3]);
                MMA16816(cu[1][2 * q],     a1, bu[0], bu[2]);
                MMA16816(cu[1][2 * q + 1], a1, bu[1], bu[3]);
            }
        }
        cOff += G1_STAGE_B; if (cOff == NSTG * G1_STAGE_B) cOff = 0;
        wOff += G1_STAGE_B; if (wOff == NSTG * G1_STAGE_B) wOff = 0;
    }
#undef G1LOAD

    // epilogue: silu(g)*u -> fp16 hidden
    int rA = wm * 32 + (lane >> 2);
    int cBase = n0 + wn * 64 + 2 * (lane & 3);
#pragma unroll
    for (int mt = 0; mt < 2; mt++) {
#pragma unroll
        for (int nt = 0; nt < 8; nt++) {
            int col = cBase + nt * 8;
            int r0r = rA + mt * 16;
            float* g0 = cg[mt][nt];
            float* u0 = cu[mt][nt];
            if (row0 + r0r < rend) {
                float h0 = u0[0] * (g0[0] / (1.f + __expf(-g0[0])));
                float h1 = u0[1] * (g0[1] / (1.f + __expf(-g0[1])));
                __half2 hv = __floats2half2_rn(h0, h1);
                *(__half2*)(g_hid + (size_t)(row0 + r0r) * I_DIM + col) = hv;
            }
            if (row0 + r0r + 8 < rend) {
                float h2 = u0[2] * (g0[2] / (1.f + __expf(-g0[2])));
                float h3 = u0[3] * (g0[3] / (1.f + __expf(-g0[3])));
                __half2 hv = __floats2half2_rn(h2, h3);
                *(__half2*)(g_hid + (size_t)(row0 + r0r + 8) * I_DIM + col) = hv;
            }
        }
    }
}

// ---------------- GEMM2: y[slot] = hidden @ down (plain stores) ----------------
__global__ void __launch_bounds__(256)
gemm2_mma() {
    extern __shared__ char dsm[];
    int tid = threadIdx.x, warp = tid >> 5, lane = tid & 31;
    int* hdr = (int*)dsm;
    resolve_tile(hdr);
    __syncthreads();
    int e = hdr[0];
    if (e < 0) return;
    int row0 = hdr[1], rend = hdr[2];
    int n0 = blockIdx.y * 128;
    uint32_t sb = smem_u32(dsm);

    int lrow = tid >> 1, seg0 = (tid & 1) * 2;
    const char* aP = (const char*)(g_hid + (size_t)(row0 + lrow) * I_DIM) + seg0 * 16;
    const char* bP = (const char*)(g_w2 + ((size_t)e * H_DIM + n0 + lrow) * I_DIM) + seg0 * 16;
    uint32_t dstBase = sb + TILE0 + lrow * RSTRB + seg0 * 16;

#define G2LOAD(bufo, k0) { \
        uint32_t d = dstBase + (bufo); int kb = (k0) * 2; \
        CPA16(d,            aP + kb); CPA16(d + 16,         aP + kb + 16); \
        CPA16(d + 10240,    bP + kb); CPA16(d + 10240 + 16, bP + kb + 16); }

    float cc[2][8][4];
#pragma unroll
    for (int i = 0; i < 2; i++)
#pragma unroll
        for (int j = 0; j < 8; j++)
#pragma unroll
            for (int q = 0; q < 4; q++) cc[i][j][q] = 0.f;

    G2LOAD(0, 0); CPCOMMIT();
    G2LOAD(G2_STAGE_B, BKH); CPCOMMIT();

    int wm = warp & 3, wn = warp >> 2;
    uint32_t aOff = TILE0 + (wm * 32 + (lane & 15)) * RSTRB + ((lane >> 4) & 1) * 16;
    uint32_t bOff = TILE0 + 10240 + (wn * 64 + (lane & 15)) * RSTRB + ((lane >> 4) & 1) * 16;

    const int NS = I_DIM / BKH;   // 64 stages
    int cOff = 0, wOff = 2 * G2_STAGE_B;
    for (int s = 0; s < NS; s++) {
        CPWAIT1();
        __syncthreads();
        if (s + 2 < NS) { G2LOAD(wOff, (s + 2) * BKH); }
        CPCOMMIT();
        uint32_t bA = sb + aOff + cOff;
        uint32_t bB = sb + bOff + cOff;
#pragma unroll
        for (int k16 = 0; k16 < 2; k16++) {
            uint32_t a0[4], a1[4];
            LDM4(a0, bA + k16 * 32);
            LDM4(a1, bA + 16 * RSTRB + k16 * 32);
#pragma unroll
            for (int q = 0; q < 4; q++) {
                uint32_t bb[4];
                LDM4(bb, bB + q * 16 * RSTRB + k16 * 32);
                MMA16816(cc[0][2 * q],     a0, bb[0], bb[2]);
                MMA16816(cc[0][2 * q + 1], a0, bb[1], bb[3]);
                MMA16816(cc[1][2 * q],     a1, bb[0], bb[2]);
                MMA16816(cc[1][2 * q + 1], a1, bb[1], bb[3]);
            }
        }
        cOff += G2_STAGE_B; if (cOff == NSTG * G2_STAGE_B) cOff = 0;
        wOff += G2_STAGE_B; if (wOff == NSTG * G2_STAGE_B) wOff = 0;
    }
#undef G2LOAD

    int rA = wm * 32 + (lane >> 2);
    int cBase = n0 + wn * 64 + 2 * (lane & 3);
#pragma unroll
    for (int mt = 0; mt < 2; mt++) {
#pragma unroll
        for (int nt = 0; nt < 8; nt++) {
            int col = cBase + nt * 8;
            int r0r = rA + mt * 16;
            float* c0 = cc[mt][nt];
            if (row0 + r0r < rend)
                *(float2*)(g_y + (size_t)(row0 + r0r) * H_DIM + col) =
                    make_float2(c0[0], c0[1]);
            if (row0 + r0r + 8 < rend)
                *(float2*)(g_y + (size_t)(row0 + r0r + 8) * H_DIM + col) =
                    make_float2(c0[2], c0[3]);
        }
    }
}

// ---------------- combine: out[t] = w0*y[slot0] + w1*y[slot1] ----------------
__global__ void combine_kernel(float* __restrict__ out) {
    int t = blockIdx.x;
    int c = threadIdx.x * 4;
    int s0 = g_slot_of[2 * t], s1 = g_slot_of[2 * t + 1];
    float w0 = g_tok_wt[2 * t], w1 = g_tok_wt[2 * t + 1];
    float4 a = *(const float4*)(g_y + (size_t)s0 * H_DIM + c);
    float4 b = *(const float4*)(g_y + (size_t)s1 * H_DIM + c);
    float4 o;
    o.x = a.x * w0 + b.x * w1;
    o.y = a.y * w0 + b.y * w1;
    o.z = a.z * w0 + b.z * w1;
    o.w = a.w * w0 + b.w * w1;
    *(float4*)(out + (size_t)t * H_DIM + c) = o;
}

// ---------------- launcher ----------------
extern "C" void kernel_launch(void* const* d_in, const int* in_sizes, int n_in,
                              void* d_out, int out_size) {
    const float* x  = (const float*)d_in[0];   // [B,S,H]
    const float* rw = (const float*)d_in[1];   // [H,E]
    const float* gw = (const float*)d_in[2];   // [E,H,I]
    const float* uw = (const float*)d_in[3];   // [E,H,I]
    const float* ow = (const float*)d_in[4];   // [E,I,H]
    float* out = (float*)d_out;

    (void)cudaFuncSetAttribute(gemm1_mma, cudaFuncAttributeMaxDynamicSharedMemorySize, G1_SMEM);
    (void)cudaFuncSetAttribute(gemm2_mma, cudaFuncAttributeMaxDynamicSharedMemorySize, G2_SMEM);

    int write_logits = (out_size >= T_TOK * H_DIM + T_TOK * E_NUM) ? 1 : 0;
    float* logits = out + (size_t)T_TOK * H_DIM;

    zero_cnt_kernel<<<1, 32>>>();
    router_kernel<<<T_TOK, 256>>>(x, rw, logits, write_logits);
    scan_off_kernel<<<1, 32>>>();
    build_perm_kernel<<<(NSLOT + 255) / 256, 256>>>();

    conv_x_kernel<<<T_TOK, 256>>>(x);
    conv_wT_kernel<<<dim3(I_DIM / 32, H_DIM / 32, E_NUM), dim3(32, 8)>>>(gw, 0, H_DIM, I_DIM);
    conv_wT_kernel<<<dim3(I_DIM / 32, H_DIM / 32, E_NUM), dim3(32, 8)>>>(uw, 1, H_DIM, I_DIM);
    conv_wT_kernel<<<dim3(H_DIM / 32, I_DIM / 32, E_NUM), dim3(32, 8)>>>(ow, 2, I_DIM, H_DIM);

    gemm1_mma<<<dim3(ROW_TILES, I_DIM / 128), 256, G1_SMEM>>>();
    gemm2_mma<<<dim3(ROW_TILES, H_DIM / 128), 256, G2_SMEM>>>();
    combine_kernel<<<T_TOK, 256>>>(out);
}

// round 15
// speedup vs baseline: 3.7991x; 1.1542x over previous
#include <cuda_runtime.h>
#include <cuda_fp16.h>
#include <cstdint>
#include <math.h>

// ---------------- problem constants ----------------
#define T_TOK   4096
#define H_DIM   1024
#define I_DIM   2048
#define E_NUM   8
#define NSLOT   (T_TOK * 2)
#define ROW_TILES 71          // sum ceil(cnt_e/128) <= 64 + 7

#define BKH   32              // K halfs per stage
#define RSTRA 80              // A row stride bytes (K-major rows)
#define RSTRB 272             // B row stride bytes (N-major rows, 256B data + 16 pad)
#define TILE0 1152            // tile region start in dynamic smem
#define NSTG  3

#define G1_A_B     (128 * RSTRA)             // 10240
#define G1_BB      (32 * RSTRB)              // 8704 per matrix
#define G1_STAGE_B (G1_A_B + 2 * G1_BB)      // 27648
#define G1_SMEM    (TILE0 + NSTG * G1_STAGE_B)
#define G2_STAGE_B (G1_A_B + G1_BB)          // 18944
#define G2_SMEM    (TILE0 + NSTG * G2_STAGE_B)

// ---------------- device scratch ----------------
__device__ int   g_cnt[E_NUM];
__device__ int   g_off[E_NUM + 1];
__device__ int   g_tok_exp[NSLOT];
__device__ float g_tok_wt[NSLOT];
__device__ int   g_tok_rank[NSLOT];
__device__ int   g_perm[NSLOT];
__device__ int   g_slot_of[NSLOT];

__device__ __half g_xh [(size_t)T_TOK * H_DIM];                // x fp16 [t][k]
__device__ __half g_wg [(size_t)E_NUM * H_DIM * I_DIM];        // gate fp16 [e][k in H][n in I]
__device__ __half g_wu [(size_t)E_NUM * H_DIM * I_DIM];        // up   fp16 same layout
__device__ __half g_w2 [(size_t)E_NUM * I_DIM * H_DIM];        // down fp16 [e][k in I][n in H]
__device__ __half g_hid[(size_t)(NSLOT + 128) * I_DIM];        // hidden fp16 [slot][k]
__device__ float  g_y  [(size_t)(NSLOT + 128) * H_DIM];        // per-slot down output

// ---------------- PTX helpers ----------------
__device__ __forceinline__ uint32_t smem_u32(const void* p) {
    uint32_t a;
    asm("{ .reg .u64 t; cvta.to.shared.u64 t, %1; cvt.u32.u64 %0, t; }" : "=r"(a) : "l"(p));
    return a;
}
#define CPA16(dst, src) \
    asm volatile("cp.async.cg.shared.global [%0], [%1], 16;" :: "r"(dst), "l"(src))
#define CPCOMMIT() asm volatile("cp.async.commit_group;" ::: "memory")
#define CPWAIT1()  asm volatile("cp.async.wait_group 1;" ::: "memory")

#define LDM4(r, addr) \
    asm volatile("ldmatrix.sync.aligned.m8n8.x4.shared.b16 {%0,%1,%2,%3}, [%4];" \
        : "=r"((r)[0]), "=r"((r)[1]), "=r"((r)[2]), "=r"((r)[3]) : "r"(addr))
#define LDM4T(r, addr) \
    asm volatile("ldmatrix.sync.aligned.m8n8.x4.trans.shared.b16 {%0,%1,%2,%3}, [%4];" \
        : "=r"((r)[0]), "=r"((r)[1]), "=r"((r)[2]), "=r"((r)[3]) : "r"(addr))

#define MMA16816(c, a, b0v, b1v) \
    asm volatile("mma.sync.aligned.m16n8k16.row.col.f32.f16.f16.f32 " \
        "{%0,%1,%2,%3}, {%4,%5,%6,%7}, {%8,%9}, {%0,%1,%2,%3};" \
        : "+f"((c)[0]), "+f"((c)[1]), "+f"((c)[2]), "+f"((c)[3]) \
        : "r"((a)[0]), "r"((a)[1]), "r"((a)[2]), "r"((a)[3]), "r"(b0v), "r"(b1v))

// ---------------- launch 0: cast all weights fp32 -> fp16 (same layout) ----------------
__global__ void conv_w_all(const float* __restrict__ gw,
                           const float* __restrict__ uw,
                           const float* __restrict__ ow) {
    if (blockIdx.x == 0 && blockIdx.y == 0 && threadIdx.x < E_NUM)
        g_cnt[threadIdx.x] = 0;
    const float* src = (blockIdx.y == 0) ? gw : (blockIdx.y == 1) ? uw : ow;
    __half* dst = (blockIdx.y == 0) ? g_wg : (blockIdx.y == 1) ? g_wu : g_w2;
    size_t i = ((size_t)blockIdx.x * blockDim.x + threadIdx.x) * 4;
    float4 v = *(const float4*)(src + i);
    __half2 a = __floats2half2_rn(v.x, v.y);
    __half2 b = __floats2half2_rn(v.z, v.w);
    *(uint2*)(dst + i) = make_uint2(*(uint32_t*)&a, *(uint32_t*)&b);
}

// ---------------- launch 1: router (+ x fp16 conversion fused) ----------------
__global__ void router_kernel(const float* __restrict__ x,
                              const float* __restrict__ rw,
                              float* __restrict__ logits_out,
                              int write_logits) {
    int t = blockIdx.x;
    int warp = threadIdx.x >> 5, lane = threadIdx.x & 31;
    const float* xr = x + (size_t)t * H_DIM;
    // fused conversion: each thread casts 4 contiguous elements
    {
        int c = threadIdx.x * 4;
        float4 v = *(const float4*)(xr + c);
        __half2 a = __floats2half2_rn(v.x, v.y);
        __half2 b = __floats2half2_rn(v.z, v.w);
        *(uint2*)(g_xh + (size_t)t * H_DIM + c) = make_uint2(*(uint32_t*)&a, *(uint32_t*)&b);
    }
    float s = 0.f;
    for (int h = lane; h < H_DIM; h += 32)
        s += xr[h] * rw[h * E_NUM + warp];
#pragma unroll
    for (int o = 16; o; o >>= 1) s += __shfl_xor_sync(0xffffffffu, s, o);
    __shared__ float lg[E_NUM];
    if (lane == 0) lg[warp] = s;
    __syncthreads();
    if (threadIdx.x == 0) {
        float l[E_NUM], mx = -1e30f;
#pragma unroll
        for (int e = 0; e < E_NUM; e++) { l[e] = lg[e]; mx = fmaxf(mx, l[e]); }
        float p[E_NUM], sum = 0.f;
#pragma unroll
        for (int e = 0; e < E_NUM; e++) { p[e] = expf(l[e] - mx); sum += p[e]; }
#pragma unroll
        for (int e = 0; e < E_NUM; e++) p[e] /= sum;
        int i1 = 0;
#pragma unroll
        for (int e = 1; e < E_NUM; e++) if (p[e] > p[i1]) i1 = e;
        int i2 = (i1 == 0) ? 1 : 0;
#pragma unroll
        for (int e = 0; e < E_NUM; e++) if (e != i1 && p[e] > p[i2]) i2 = e;
        float denom = p[i1] + p[i2];
        int r1 = atomicAdd(&g_cnt[i1], 1);
        int r2 = atomicAdd(&g_cnt[i2], 1);
        g_tok_exp[2 * t]     = i1; g_tok_wt[2 * t]     = p[i1] / denom; g_tok_rank[2 * t]     = r1;
        g_tok_exp[2 * t + 1] = i2; g_tok_wt[2 * t + 1] = p[i2] / denom; g_tok_rank[2 * t + 1] = r2;
        if (write_logits) {
#pragma unroll
            for (int e = 0; e < E_NUM; e++)
                logits_out[(size_t)t * E_NUM + e] = l[e];
        }
    }
}

// ---------------- launch 2: scan offsets + build permutation (one block) ----------------
__global__ void scanperm_kernel() {
    __shared__ int off[E_NUM + 1];
    if (threadIdx.x == 0) {
        int a = 0;
        for (int e = 0; e < E_NUM; e++) { off[e] = a; g_off[e] = a; a += g_cnt[e]; }
        off[E_NUM] = a; g_off[E_NUM] = a;
    }
    __syncthreads();
    for (int idx = threadIdx.x; idx < NSLOT; idx += blockDim.x) {
        int e = g_tok_exp[idx];
        int slot = off[e] + g_tok_rank[idx];
        g_perm[slot] = idx >> 1;
        g_slot_of[idx] = slot;
    }
}

// ---------------- tile resolver ----------------
__device__ __forceinline__ void resolve_tile(int* hdr) {
    if (threadIdx.x == 0) {
        int b = blockIdx.x, acc = 0, fe = -1, fr = 0, fn = 0;
        for (int e = 0; e < E_NUM; e++) {
            int c = g_off[e + 1] - g_off[e];
            int nt = (c + 127) >> 7;
            if (fe < 0 && b < acc + nt) { fe = e; fr = g_off[e] + (b - acc) * 128; fn = g_off[e] + c; }
            acc += nt;
        }
        hdr[0] = fe; hdr[1] = fr; hdr[2] = fn;
    }
}

// ---------------- launch 3: GEMM1 hidden = silu(x@gate)*(x@up) ----------------
__global__ void __launch_bounds__(256)
gemm1_mma() {
    extern __shared__ char dsm[];
    int tid = threadIdx.x, warp = tid >> 5, lane = tid & 31;
    int* hdr = (int*)dsm;
    int* s_tok = (int*)(dsm + 64);
    resolve_tile(hdr);
    __syncthreads();
    int e = hdr[0];
    if (e < 0) return;
    int row0 = hdr[1], rend = hdr[2];
    int n0 = blockIdx.y * 128;
    if (tid < 128) {
        int r = row0 + tid;
        s_tok[tid] = g_perm[(r < rend) ? r : row0];
    }
    __syncthreads();
    uint32_t sb = smem_u32(dsm);

    // A loads: row = tid>>1 (K-major, 64B rows), 2x16B
    int lrow = tid >> 1, seg0 = (tid & 1) * 2;
    const char* aP = (const char*)(g_xh + (size_t)s_tok[lrow] * H_DIM) + seg0 * 16;
    uint32_t dA0 = sb + TILE0 + lrow * RSTRA + seg0 * 16;
    // B loads: [K][N] rows; row r = tid>>3, chunk c = tid&7 (two 16B: c, c+8)
    int brow = tid >> 3, bc = tid & 7;
    const char* gP = (const char*)(g_wg + ((size_t)e * H_DIM + brow) * I_DIM + n0 + bc * 8);
    const char* uP = (const char*)(g_wu + ((size_t)e * H_DIM + brow) * I_DIM + n0 + bc * 8);
    uint32_t dB0 = sb + TILE0 + G1_A_B + brow * RSTRB + bc * 16;

#define G1LOAD(bufo, k0) { \
        int ka = (k0) * 2; \
        CPA16(dA0 + (bufo), aP + ka); CPA16(dA0 + (bufo) + 16, aP + ka + 16); \
        int kb = (k0) * (I_DIM * 2); \
        CPA16(dB0 + (bufo),                 gP + kb); CPA16(dB0 + (bufo) + 128,         gP + kb + 128); \
        CPA16(dB0 + (bufo) + G1_BB,         uP + kb); CPA16(dB0 + (bufo) + G1_BB + 128, uP + kb + 128); }

    float cg[2][8][4], cu[2][8][4];
#pragma unroll
    for (int i = 0; i < 2; i++)
#pragma unroll
        for (int j = 0; j < 8; j++)
#pragma unroll
            for (int q = 0; q < 4; q++) { cg[i][j][q] = 0.f; cu[i][j][q] = 0.f; }

    G1LOAD(0, 0); CPCOMMIT();
    G1LOAD(G1_STAGE_B, BKH); CPCOMMIT();

    int wm = warp & 3, wn = warp >> 2;                  // 4m x 2n warps
    uint32_t aOff = TILE0 + (wm * 32 + (lane & 15)) * RSTRA + ((lane >> 4) & 1) * 16;
    // B trans ldmatrix: grp = lane>>3, j = lane&7
    // row = k16*16 + (grp&1)*8 + j ; col = wn*64 + q*16 + (grp>>1)*8
    {
    }
    int grp = lane >> 3, bj = lane & 7;
    uint32_t bOff = TILE0 + G1_A_B + ((grp & 1) * 8 + bj) * RSTRB
                  + (wn * 64 + (grp >> 1) * 8) * 2;

    const int NS = H_DIM / BKH;   // 32 stages
    int cOff = 0, wOff = 2 * G1_STAGE_B;
    for (int s = 0; s < NS; s++) {
        CPWAIT1();
        __syncthreads();
        if (s + 2 < NS) { G1LOAD(wOff, (s + 2) * BKH); }
        CPCOMMIT();
        uint32_t bA = sb + aOff + cOff;
        uint32_t bB = sb + bOff + cOff;
#pragma unroll
        for (int k16 = 0; k16 < 2; k16++) {
            uint32_t a0[4], a1[4];
            LDM4(a0, bA + k16 * 32);
            LDM4(a1, bA + 16 * RSTRA + k16 * 32);
#pragma unroll
            for (int q = 0; q < 4; q++) {
                uint32_t bg[4], bu[4];
                LDM4T(bg, bB + k16 * (16 * RSTRB) + q * 32);
                LDM4T(bu, bB + G1_BB + k16 * (16 * RSTRB) + q * 32);
                MMA16816(cg[0][2 * q],     a0, bg[0], bg[1]);
                MMA16816(cg[0][2 * q + 1], a0, bg[2], bg[3]);
                MMA16816(cg[1][2 * q],     a1, bg[0], bg[1]);
                MMA16816(cg[1][2 * q + 1], a1, bg[2], bg[3]);
                MMA16816(cu[0][2 * q],     a0, bu[0], bu[1]);
                MMA16816(cu[0][2 * q + 1], a0, bu[2], bu[3]);
                MMA16816(cu[1][2 * q],     a1, bu[0], bu[1]);
                MMA16816(cu[1][2 * q + 1], a1, bu[2], bu[3]);
            }
        }
        cOff += G1_STAGE_B; if (cOff == NSTG * G1_STAGE_B) cOff = 0;
        wOff += G1_STAGE_B; if (wOff == NSTG * G1_STAGE_B) wOff = 0;
    }
#undef G1LOAD

    // epilogue: silu(g)*u -> fp16 hidden
    int rA = wm * 32 + (lane >> 2);
    int cBase = n0 + wn * 64 + 2 * (lane & 3);
#pragma unroll
    for (int mt = 0; mt < 2; mt++) {
#pragma unroll
        for (int nt = 0; nt < 8; nt++) {
            int col = cBase + nt * 8;
            int r0r = rA + mt * 16;
            float* g0 = cg[mt][nt];
            float* u0 = cu[mt][nt];
            if (row0 + r0r < rend) {
                float h0 = u0[0] * (g0[0] / (1.f + __expf(-g0[0])));
                float h1 = u0[1] * (g0[1] / (1.f + __expf(-g0[1])));
                __half2 hv = __floats2half2_rn(h0, h1);
                *(__half2*)(g_hid + (size_t)(row0 + r0r) * I_DIM + col) = hv;
            }
            if (row0 + r0r + 8 < rend) {
                float h2 = u0[2] * (g0[2] / (1.f + __expf(-g0[2])));
                float h3 = u0[3] * (g0[3] / (1.f + __expf(-g0[3])));
                __half2 hv = __floats2half2_rn(h2, h3);
                *(__half2*)(g_hid + (size_t)(row0 + r0r + 8) * I_DIM + col) = hv;
            }
        }
    }
}

// ---------------- launch 4: GEMM2 y[slot] = hidden @ down ----------------
__global__ void __launch_bounds__(256)
gemm2_mma() {
    extern __shared__ char dsm[];
    int tid = threadIdx.x, warp = tid >> 5, lane = tid & 31;
    int* hdr = (int*)dsm;
    resolve_tile(hdr);
    __syncthreads();
    int e = hdr[0];
    if (e < 0) return;
    int row0 = hdr[1], rend = hdr[2];
    int n0 = blockIdx.y * 128;
    uint32_t sb = smem_u32(dsm);

    int lrow = tid >> 1, seg0 = (tid & 1) * 2;
    const char* aP = (const char*)(g_hid + (size_t)(row0 + lrow) * I_DIM) + seg0 * 16;
    uint32_t dA0 = sb + TILE0 + lrow * RSTRA + seg0 * 16;
    int brow = tid >> 3, bc = tid & 7;
    const char* bP = (const char*)(g_w2 + ((size_t)e * I_DIM + brow) * H_DIM + n0 + bc * 8);
    uint32_t dB0 = sb + TILE0 + G1_A_B + brow * RSTRB + bc * 16;

#define G2LOAD(bufo, k0) { \
        int ka = (k0) * 2; \
        CPA16(dA0 + (bufo), aP + ka); CPA16(dA0 + (bufo) + 16, aP + ka + 16); \
        int kb = (k0) * (H_DIM * 2); \
        CPA16(dB0 + (bufo), bP + kb); CPA16(dB0 + (bufo) + 128, bP + kb + 128); }

    float cc[2][8][4];
#pragma unroll
    for (int i = 0; i < 2; i++)
#pragma unroll
        for (int j = 0; j < 8; j++)
#pragma unroll
            for (int q = 0; q < 4; q++) cc[i][j][q] = 0.f;

    G2LOAD(0, 0); CPCOMMIT();
    G2LOAD(G2_STAGE_B, BKH); CPCOMMIT();

    int wm = warp & 3, wn = warp >> 2;
    uint32_t aOff = TILE0 + (wm * 32 + (lane & 15)) * RSTRA + ((lane >> 4) & 1) * 16;
    int grp = lane >> 3, bj = lane & 7;
    uint32_t bOff = TILE0 + G1_A_B + ((grp & 1) * 8 + bj) * RSTRB
                  + (wn * 64 + (grp >> 1) * 8) * 2;

    const int NS = I_DIM / BKH;   // 64 stages
    int cOff = 0, wOff = 2 * G2_STAGE_B;
    for (int s = 0; s < NS; s++) {
        CPWAIT1();
        __syncthreads();
        if (s + 2 < NS) { G2LOAD(wOff, (s + 2) * BKH); }
        CPCOMMIT();
        uint32_t bA = sb + aOff + cOff;
        uint32_t bB = sb + bOff + cOff;
#pragma unroll
        for (int k16 = 0; k16 < 2; k16++) {
            uint32_t a0[4], a1[4];
            LDM4(a0, bA + k16 * 32);
            LDM4(a1, bA + 16 * RSTRA + k16 * 32);
#pragma unroll
            for (int q = 0; q < 4; q++) {
                uint32_t bb[4];
                LDM4T(bb, bB + k16 * (16 * RSTRB) + q * 32);
                MMA16816(cc[0][2 * q],     a0, bb[0], bb[1]);
                MMA16816(cc[0][2 * q + 1], a0, bb[2], bb[3]);
                MMA16816(cc[1][2 * q],     a1, bb[0], bb[1]);
                MMA16816(cc[1][2 * q + 1], a1, bb[2], bb[3]);
            }
        }
        cOff += G2_STAGE_B; if (cOff == NSTG * G2_STAGE_B) cOff = 0;
        wOff += G2_STAGE_B; if (wOff == NSTG * G2_STAGE_B) wOff = 0;
    }
#undef G2LOAD

    int rA = wm * 32 + (lane >> 2);
    int cBase = n0 + wn * 64 + 2 * (lane & 3);
#pragma unroll
    for (int mt = 0; mt < 2; mt++) {
#pragma unroll
        for (int nt = 0; nt < 8; nt++) {
            int col = cBase + nt * 8;
            int r0r = rA + mt * 16;
            float* c0 = cc[mt][nt];
            if (row0 + r0r < rend)
                *(float2*)(g_y + (size_t)(row0 + r0r) * H_DIM + col) =
                    make_float2(c0[0], c0[1]);
            if (row0 + r0r + 8 < rend)
                *(float2*)(g_y + (size_t)(row0 + r0r + 8) * H_DIM + col) =
                    make_float2(c0[2], c0[3]);
        }
    }
}

// ---------------- launch 5: combine out[t] = w0*y[slot0] + w1*y[slot1] ----------------
__global__ void combine_kernel(float* __restrict__ out) {
    int t = blockIdx.x;
    int c = threadIdx.x * 4;
    int s0 = g_slot_of[2 * t], s1 = g_slot_of[2 * t + 1];
    float w0 = g_tok_wt[2 * t], w1 = g_tok_wt[2 * t + 1];
    float4 a = *(const float4*)(g_y + (size_t)s0 * H_DIM + c);
    float4 b = *(const float4*)(g_y + (size_t)s1 * H_DIM + c);
    float4 o;
    o.x = a.x * w0 + b.x * w1;
    o.y = a.y * w0 + b.y * w1;
    o.z = a.z * w0 + b.z * w1;
    o.w = a.w * w0 + b.w * w1;
    *(float4*)(out + (size_t)t * H_DIM + c) = o;
}

// ---------------- launcher ----------------
extern "C" void kernel_launch(void* const* d_in, const int* in_sizes, int n_in,
                              void* d_out, int out_size) {
    const float* x  = (const float*)d_in[0];   // [B,S,H]
    const float* rw = (const float*)d_in[1];   // [H,E]
    const float* gw = (const float*)d_in[2];   // [E,H,I]
    const float* uw = (const float*)d_in[3];   // [E,H,I]
    const float* ow = (const float*)d_in[4];   // [E,I,H]
    float* out = (float*)d_out;

    (void)cudaFuncSetAttribute(gemm1_mma, cudaFuncAttributeMaxDynamicSharedMemorySize, G1_SMEM);
    (void)cudaFuncSetAttribute(gemm2_mma, cudaFuncAttributeMaxDynamicSharedMemorySize, G2_SMEM);

    int write_logits = (out_size >= T_TOK * H_DIM + T_TOK * E_NUM) ? 1 : 0;
    float* logits = out + (size_t)T_TOK * H_DIM;

    // (E*H*I)/4 elements per thread-block-row: 16777216/4/256 = 16384 blocks
    conv_w_all<<<dim3(16384, 3), 256>>>(gw, uw, ow);             // launch 0 (+cnt zero)
    router_kernel<<<T_TOK, 256>>>(x, rw, logits, write_logits);  // launch 1 (+x cast)
    scanperm_kernel<<<1, 256>>>();                               // launch 2
    gemm1_mma<<<dim3(ROW_TILES, I_DIM / 128), 256, G1_SMEM>>>(); // launch 3  <- ncu target
    gemm2_mma<<<dim3(ROW_TILES, H_DIM / 128), 256, G2_SMEM>>>(); // launch 4
    combine_kernel<<<T_TOK, 256>>>(out);                         // launch 5
}